// round 1
// baseline (speedup 1.0000x reference)
#include <cuda_runtime.h>
#include <cuda_bf16.h>
#include <cstdint>

#define NNODE 4096
#define FD 256
#define HD 256
#define KEXP 3
#define TSTEP 5
#define G4 1024
#define SIG_LO 10
#define SIG_HI 253   // F_DIM - END = 256 - 3

// ---------------- scratch (device globals: no allocation allowed) ----------------
__device__ __nv_bfloat16 g_A[KEXP][(size_t)NNODE * NNODE];   // a_bin + I, {0,1,2}
__device__ float g_dinv[KEXP][NNODE];
__device__ float g_y[(size_t)NNODE * HD];      // dinv_j * (x @ gnn_w)
__device__ float g_xt[(size_t)NNODE * HD];     // gnn_out (LSTM input)
__device__ float g_gx[(size_t)NNODE * G4];     // xt@Wih^T + b_ih + b_hh (time-invariant)
__device__ float g_hhbuf[(size_t)NNODE * G4];  // h@Whh^T
__device__ float g_h[(size_t)NNODE * HD];
__device__ float g_c[(size_t)NNODE * HD];
__device__ float g_pre[(size_t)NNODE * FD];    // fc pre-activation
__device__ float g_dsum[(size_t)NNODE * FD];   // sum of deltas over k

__device__ __forceinline__ float sigf(float v) { return 1.0f / (1.0f + expf(-v)); }

// ---------------- prep: one coalesced pass over adj ----------------
// builds bf16 A_k = a_bin + I, degrees -> dinv, and the float adj passthrough.
__global__ void prep_kernel(const int* __restrict__ adj, float* __restrict__ out_adj) {
    const int i = blockIdx.x;
    const int tid = threadIdx.x;
    const int* row = adj + (size_t)i * NNODE * KEXP;
    float* orow = out_adj + (size_t)i * NNODE * KEXP;
    __nv_bfloat16* A0 = &g_A[0][(size_t)i * NNODE];
    __nv_bfloat16* A1 = &g_A[1][(size_t)i * NNODE];
    __nv_bfloat16* A2 = &g_A[2][(size_t)i * NNODE];
    float s0 = 0.f, s1 = 0.f, s2 = 0.f;
    for (int j = tid; j < NNODE; j += 256) {
        int b = j * 3;
        int a0 = row[b + 0], a1 = row[b + 1], a2 = row[b + 2];
        float v0 = a0 ? 1.f : 0.f, v1 = a1 ? 1.f : 0.f, v2 = a2 ? 1.f : 0.f;
        if (j == i) { v0 += 1.f; v1 += 1.f; v2 += 1.f; }   // self-loop on top of existing edge
        A0[j] = __float2bfloat16(v0);
        A1[j] = __float2bfloat16(v1);
        A2[j] = __float2bfloat16(v2);
        orow[b + 0] = (float)a0; orow[b + 1] = (float)a1; orow[b + 2] = (float)a2;
        s0 += v0; s1 += v1; s2 += v2;
    }
    __shared__ float sh[3][256];
    sh[0][tid] = s0; sh[1][tid] = s1; sh[2][tid] = s2;
    __syncthreads();
    for (int off = 128; off > 0; off >>= 1) {
        if (tid < off) {
            sh[0][tid] += sh[0][tid + off];
            sh[1][tid] += sh[1][tid + off];
            sh[2][tid] += sh[2][tid + off];
        }
        __syncthreads();
    }
    if (tid < 3) g_dinv[tid][i] = rsqrtf(sh[tid][0]);   // deg >= 1 always (self-loop)
}

// ---------------- y = dinv[:,None] * (x @ gnn_w[k]) : NN GEMM 4096x256x256 ----------------
__global__ void gemm_xw(const float* __restrict__ X, const float* __restrict__ W, int k) {
    __shared__ float As[16][68];
    __shared__ float Bs[16][68];
    const float* __restrict__ dinv = g_dinv[k];
    const int bm = blockIdx.y * 64, bn = blockIdx.x * 64;
    const int tid = threadIdx.x, ty = tid >> 4, tx = tid & 15;
    float acc[4][4] = {};
    for (int k0 = 0; k0 < FD; k0 += 16) {
        {
            int m = tid >> 2, kq = (tid & 3) * 4;
            float4 v = *(const float4*)(X + (size_t)(bm + m) * FD + k0 + kq);
            As[kq + 0][m] = v.x; As[kq + 1][m] = v.y; As[kq + 2][m] = v.z; As[kq + 3][m] = v.w;
        }
        {
            int kk = tid >> 4, nq = (tid & 15) * 4;
            *(float4*)&Bs[kk][nq] = *(const float4*)(W + (size_t)(k0 + kk) * HD + bn + nq);
        }
        __syncthreads();
        #pragma unroll
        for (int kk = 0; kk < 16; kk++) {
            float a[4], b[4];
            #pragma unroll
            for (int i = 0; i < 4; i++) a[i] = As[kk][ty * 4 + i];
            #pragma unroll
            for (int j = 0; j < 4; j++) b[j] = Bs[kk][tx * 4 + j];
            #pragma unroll
            for (int i = 0; i < 4; i++)
                #pragma unroll
                for (int j = 0; j < 4; j++) acc[i][j] = fmaf(a[i], b[j], acc[i][j]);
        }
        __syncthreads();
    }
    #pragma unroll
    for (int i = 0; i < 4; i++) {
        int row = bm + ty * 4 + i;
        float s = dinv[row];
        #pragma unroll
        for (int j = 0; j < 4; j++)
            g_y[(size_t)row * HD + bn + tx * 4 + j] = s * acc[i][j];
    }
}

// ---------------- gnn_out = dinv_i * (A_k @ y) + gnn_b : NN GEMM 4096x256x4096, A bf16 ----------------
__global__ void gemm_gcn(int k, const float* __restrict__ bias) {
    __shared__ float As[16][68];
    __shared__ float Bs[16][68];
    const __nv_bfloat16* __restrict__ A = g_A[k];
    const float* __restrict__ dinv = g_dinv[k];
    const int bm = blockIdx.y * 64, bn = blockIdx.x * 64;
    const int tid = threadIdx.x, ty = tid >> 4, tx = tid & 15;
    float acc[4][4] = {};
    for (int k0 = 0; k0 < NNODE; k0 += 16) {
        {
            int m = tid >> 2, kq = (tid & 3) * 4;
            const __nv_bfloat16* p = A + (size_t)(bm + m) * NNODE + k0 + kq;
            float2 raw = *(const float2*)p;  // 4 bf16, 8B aligned
            __nv_bfloat162 lo = *(__nv_bfloat162*)&raw.x;
            __nv_bfloat162 hi = *(__nv_bfloat162*)&raw.y;
            float2 f0 = __bfloat1622float2(lo);
            float2 f1 = __bfloat1622float2(hi);
            As[kq + 0][m] = f0.x; As[kq + 1][m] = f0.y; As[kq + 2][m] = f1.x; As[kq + 3][m] = f1.y;
        }
        {
            int kk = tid >> 4, nq = (tid & 15) * 4;
            *(float4*)&Bs[kk][nq] = *(const float4*)(g_y + (size_t)(k0 + kk) * HD + bn + nq);
        }
        __syncthreads();
        #pragma unroll
        for (int kk = 0; kk < 16; kk++) {
            float a[4], b[4];
            #pragma unroll
            for (int i = 0; i < 4; i++) a[i] = As[kk][ty * 4 + i];
            #pragma unroll
            for (int j = 0; j < 4; j++) b[j] = Bs[kk][tx * 4 + j];
            #pragma unroll
            for (int i = 0; i < 4; i++)
                #pragma unroll
                for (int j = 0; j < 4; j++) acc[i][j] = fmaf(a[i], b[j], acc[i][j]);
        }
        __syncthreads();
    }
    #pragma unroll
    for (int i = 0; i < 4; i++) {
        int row = bm + ty * 4 + i;
        float s = dinv[row];
        #pragma unroll
        for (int j = 0; j < 4; j++) {
            int col = bn + tx * 4 + j;
            g_xt[(size_t)row * HD + col] = s * acc[i][j] + bias[col];
        }
    }
}

// ---------------- C[M=4096, Nn] = A[4096,256] @ B[Nn,256]^T (+bias +bias2) ----------------
// BM=128, BN=64, BK=16, 256 threads, 8x4 micro-tile.
__global__ void gemm_nt(const float* __restrict__ A, const float* __restrict__ B,
                        const float* __restrict__ bias, const float* __restrict__ bias2,
                        float* __restrict__ C, int Nn) {
    __shared__ float As[16][132];
    __shared__ float Bs[16][68];
    const int bm = blockIdx.y * 128, bn = blockIdx.x * 64;
    const int tid = threadIdx.x, ty = tid >> 4, tx = tid & 15;
    const int Kd = HD;  // 256
    float acc[8][4] = {};
    for (int k0 = 0; k0 < Kd; k0 += 16) {
        {
            int m = tid >> 1, kq = (tid & 1) * 8;
            const float* p = A + (size_t)(bm + m) * Kd + k0 + kq;
            float4 v0 = *(const float4*)p;
            float4 v1 = *(const float4*)(p + 4);
            As[kq + 0][m] = v0.x; As[kq + 1][m] = v0.y; As[kq + 2][m] = v0.z; As[kq + 3][m] = v0.w;
            As[kq + 4][m] = v1.x; As[kq + 5][m] = v1.y; As[kq + 6][m] = v1.z; As[kq + 7][m] = v1.w;
        }
        {
            int n = tid >> 2, kq = (tid & 3) * 4;
            float4 v = *(const float4*)(B + (size_t)(bn + n) * Kd + k0 + kq);
            Bs[kq + 0][n] = v.x; Bs[kq + 1][n] = v.y; Bs[kq + 2][n] = v.z; Bs[kq + 3][n] = v.w;
        }
        __syncthreads();
        #pragma unroll
        for (int kk = 0; kk < 16; kk++) {
            float a[8], b[4];
            #pragma unroll
            for (int i = 0; i < 8; i++) a[i] = As[kk][ty * 8 + i];
            #pragma unroll
            for (int j = 0; j < 4; j++) b[j] = Bs[kk][tx * 4 + j];
            #pragma unroll
            for (int i = 0; i < 8; i++)
                #pragma unroll
                for (int j = 0; j < 4; j++) acc[i][j] = fmaf(a[i], b[j], acc[i][j]);
        }
        __syncthreads();
    }
    #pragma unroll
    for (int i = 0; i < 8; i++) {
        int row = bm + ty * 8 + i;
        #pragma unroll
        for (int j = 0; j < 4; j++) {
            int col = bn + tx * 4 + j;
            float v = acc[i][j];
            if (bias)  v += bias[col];
            if (bias2) v += bias2[col];
            C[(size_t)row * Nn + col] = v;
        }
    }
}

// ---------------- LSTM gate update ----------------
__global__ void lstm_gate(int use_hh, int first) {
    int idx = blockIdx.x * blockDim.x + threadIdx.x;   // < NNODE*HD
    int n = idx >> 8, f = idx & 255;
    size_t base = (size_t)n * G4;
    float gi = g_gx[base + f];
    float gf = g_gx[base + 256 + f];
    float gg = g_gx[base + 512 + f];
    float go = g_gx[base + 768 + f];
    if (use_hh) {
        gi += g_hhbuf[base + f];
        gf += g_hhbuf[base + 256 + f];
        gg += g_hhbuf[base + 512 + f];
        go += g_hhbuf[base + 768 + f];
    }
    float cp = first ? 0.f : g_c[idx];
    float cn = sigf(gf) * cp + sigf(gi) * tanhf(gg);
    g_c[idx] = cn;
    g_h[idx] = sigf(go) * tanhf(cn);
}

// ---------------- fc epilogue: delta=tanh(pre); zbar=sigslice(x+delta); dsum += delta ----------------
__global__ void fc_post(const float* __restrict__ x, float* __restrict__ out_zbar, int k) {
    int idx = blockIdx.x * blockDim.x + threadIdx.x;
    int f = idx & 255;
    float d = tanhf(g_pre[idx]);
    float z = x[idx] + d;
    if (f >= SIG_LO && f < SIG_HI) z = sigf(z);
    out_zbar[(size_t)idx * KEXP + k] = z;
    g_dsum[idx] = (k == 0) ? d : (g_dsum[idx] + d);
}

__global__ void final_pred(const float* __restrict__ x, float* __restrict__ out_pred) {
    int idx = blockIdx.x * blockDim.x + threadIdx.x;
    int f = idx & 255;
    float z = x[idx] + g_dsum[idx] * (1.0f / 3.0f);
    if (f >= SIG_LO && f < SIG_HI) z = sigf(z);
    out_pred[idx] = z;
}

// ---------------- launcher ----------------
extern "C" void kernel_launch(void* const* d_in, const int* in_sizes, int n_in,
                              void* d_out, int out_size) {
    const float* x     = (const float*)d_in[0];
    const float* gnn_w = (const float*)d_in[1];
    const float* gnn_b = (const float*)d_in[2];
    const float* w_ih  = (const float*)d_in[3];
    const float* w_hh  = (const float*)d_in[4];
    const float* b_ih  = (const float*)d_in[5];
    const float* b_hh  = (const float*)d_in[6];
    const float* fc_w  = (const float*)d_in[7];
    const float* fc_b  = (const float*)d_in[8];
    const int*   adj   = (const int*)d_in[9];

    float* out = (float*)d_out;
    float* out_pred = out;                                   // [N, F]
    float* out_zbar = out + (size_t)NNODE * FD;              // [N, F, K]
    float* out_adj  = out + (size_t)NNODE * FD * 4;          // [N, N, K] as float

    float *p_xt, *p_h, *p_gx, *p_hh, *p_pre;
    cudaGetSymbolAddress((void**)&p_xt,  g_xt);
    cudaGetSymbolAddress((void**)&p_h,   g_h);
    cudaGetSymbolAddress((void**)&p_gx,  g_gx);
    cudaGetSymbolAddress((void**)&p_hh,  g_hhbuf);
    cudaGetSymbolAddress((void**)&p_pre, g_pre);

    prep_kernel<<<NNODE, 256>>>(adj, out_adj);

    const int EW_BLOCKS = (NNODE * FD) / 256;

    for (int k = 0; k < KEXP; k++) {
        gemm_xw<<<dim3(HD / 64, NNODE / 64), 256>>>(x, gnn_w + (size_t)k * FD * HD, k);
        gemm_gcn<<<dim3(HD / 64, NNODE / 64), 256>>>(k, gnn_b + (size_t)k * HD);

        // time-invariant input projection: gx = xt@Wih^T + b_ih + b_hh
        gemm_nt<<<dim3(G4 / 64, NNODE / 128), 256>>>(
            p_xt, w_ih + (size_t)k * G4 * HD,
            b_ih + (size_t)k * G4, b_hh + (size_t)k * G4, p_gx, G4);

        lstm_gate<<<EW_BLOCKS, 256>>>(0, 1);   // t=0: h=c=0
        for (int t = 1; t < TSTEP; t++) {
            gemm_nt<<<dim3(G4 / 64, NNODE / 128), 256>>>(
                p_h, w_hh + (size_t)k * G4 * HD, nullptr, nullptr, p_hh, G4);
            lstm_gate<<<EW_BLOCKS, 256>>>(1, 0);
        }

        gemm_nt<<<dim3(FD / 64, NNODE / 128), 256>>>(
            p_h, fc_w + (size_t)k * FD * HD, fc_b + (size_t)k * FD, nullptr, p_pre, FD);
        fc_post<<<EW_BLOCKS, 256>>>(x, out_zbar, k);
    }

    final_pred<<<EW_BLOCKS, 256>>>(x, out_pred);
}

// round 2
// speedup vs baseline: 1.2632x; 1.2632x over previous
#include <cuda_runtime.h>
#include <cuda_bf16.h>
#include <cstdint>

#define NNODE 4096
#define FD 256
#define HD 256
#define KEXP 3
#define TSTEP 5
#define G4 1024
#define SIG_LO 10
#define SIG_HI 253   // F_DIM - END

// ---------------- scratch (device globals: no allocation allowed) ----------------
__device__ float g_Af[KEXP][(size_t)NNODE * NNODE];   // a_bin + I, values {0,1,2}
__device__ float g_dinv[KEXP][NNODE];
__device__ float g_y[(size_t)NNODE * HD];      // dinv_j * (x @ gnn_w)
__device__ float g_xt[(size_t)NNODE * HD];     // gnn_out (LSTM input)
__device__ float g_gx[(size_t)NNODE * G4];     // xt@Wih^T + b_ih + b_hh (time-invariant)
__device__ float g_hhbuf[(size_t)NNODE * G4];  // h@Whh^T
__device__ float g_h[(size_t)NNODE * HD];
__device__ float g_c[(size_t)NNODE * HD];
__device__ float g_pre[(size_t)NNODE * FD];    // fc pre-activation
__device__ float g_dsum[(size_t)NNODE * FD];   // sum of deltas over k

__device__ __forceinline__ float sigf(float v) { return 1.0f / (1.0f + expf(-v)); }

__device__ __forceinline__ uint32_t f2tf(float f) {
    uint32_t r;
    asm("cvt.rna.tf32.f32 %0, %1;" : "=r"(r) : "f"(f));
    return r;
}

__device__ __forceinline__ void mma_tf32(float c[4], const uint32_t a[4], const uint32_t b[2]) {
    asm volatile(
        "mma.sync.aligned.m16n8k8.row.col.f32.tf32.tf32.f32 "
        "{%0,%1,%2,%3}, {%4,%5,%6,%7}, {%8,%9}, {%0,%1,%2,%3};"
        : "+f"(c[0]), "+f"(c[1]), "+f"(c[2]), "+f"(c[3])
        : "r"(a[0]), "r"(a[1]), "r"(a[2]), "r"(a[3]), "r"(b[0]), "r"(b[1]));
}

// ---------------- prep: one coalesced pass over adj ----------------
__global__ void prep_kernel(const int* __restrict__ adj, float* __restrict__ out_adj) {
    const int i = blockIdx.x;
    const int tid = threadIdx.x;
    const int* row = adj + (size_t)i * NNODE * KEXP;
    float* orow = out_adj + (size_t)i * NNODE * KEXP;
    float* A0 = &g_Af[0][(size_t)i * NNODE];
    float* A1 = &g_Af[1][(size_t)i * NNODE];
    float* A2 = &g_Af[2][(size_t)i * NNODE];
    float s0 = 0.f, s1 = 0.f, s2 = 0.f;
    for (int j = tid; j < NNODE; j += 256) {
        int b = j * 3;
        int a0 = row[b + 0], a1 = row[b + 1], a2 = row[b + 2];
        float v0 = a0 ? 1.f : 0.f, v1 = a1 ? 1.f : 0.f, v2 = a2 ? 1.f : 0.f;
        if (j == i) { v0 += 1.f; v1 += 1.f; v2 += 1.f; }
        A0[j] = v0; A1[j] = v1; A2[j] = v2;
        orow[b + 0] = (float)a0; orow[b + 1] = (float)a1; orow[b + 2] = (float)a2;
        s0 += v0; s1 += v1; s2 += v2;
    }
    __shared__ float sh[3][256];
    sh[0][tid] = s0; sh[1][tid] = s1; sh[2][tid] = s2;
    __syncthreads();
    for (int off = 128; off > 0; off >>= 1) {
        if (tid < off) {
            sh[0][tid] += sh[0][tid + off];
            sh[1][tid] += sh[1][tid + off];
            sh[2][tid] += sh[2][tid + off];
        }
        __syncthreads();
    }
    if (tid < 3) g_dinv[tid][i] = rsqrtf(sh[tid][0]);
}

// ---------------- TF32 tensor-core GEMM ----------------
// C[M,Nn] = A[M,Kd] @ op(B)  (+ rowscale + bias + bias2)
// TRANSB=0: B is [Kd,Nn] row-major (NN).  TRANSB=1: B is [Nn,Kd] row-major (NT).
// Tile: 64x64x32, 256 threads = 8 warps (2 x 4), warp tile 32x16, mma m16n8k8.
template <int TRANSB>
__global__ void __launch_bounds__(256) mma_gemm(
    const float* __restrict__ A, const float* __restrict__ B,
    const float* __restrict__ rowscale, const float* __restrict__ bias,
    const float* __restrict__ bias2, float* __restrict__ C, int Nn, int Kd) {
    __shared__ uint32_t As[32][72];   // [k][m], (72 % 32)==8 -> conflict-free frag loads
    __shared__ uint32_t Bs[32][72];   // [k][n]

    const int tid = threadIdx.x;
    const int wid = tid >> 5, lane = tid & 31;
    const int warp_m = wid >> 2;          // 0..1
    const int warp_n = wid & 3;           // 0..3
    const int g = lane >> 2, c4 = lane & 3;
    const int bm = blockIdx.y * 64, bn = blockIdx.x * 64;

    // staging assignment (A and NT-B): m/n = tid&63, k-group = tid>>6
    const int sm = tid & 63, skg = tid >> 6;

    float acc[2][2][4] = {};

    for (int k0 = 0; k0 < Kd; k0 += 32) {
        // ---- stage A tile (transpose to [k][m]) ----
        {
            const float* ap = A + (size_t)(bm + sm) * Kd + k0 + skg * 8;
            float4 v0 = *(const float4*)ap;
            float4 v1 = *(const float4*)(ap + 4);
            As[skg * 8 + 0][sm] = f2tf(v0.x); As[skg * 8 + 1][sm] = f2tf(v0.y);
            As[skg * 8 + 2][sm] = f2tf(v0.z); As[skg * 8 + 3][sm] = f2tf(v0.w);
            As[skg * 8 + 4][sm] = f2tf(v1.x); As[skg * 8 + 5][sm] = f2tf(v1.y);
            As[skg * 8 + 6][sm] = f2tf(v1.z); As[skg * 8 + 7][sm] = f2tf(v1.w);
        }
        // ---- stage B tile to [k][n] ----
        if (TRANSB) {
            const float* bp = B + (size_t)(bn + sm) * Kd + k0 + skg * 8;
            float4 v0 = *(const float4*)bp;
            float4 v1 = *(const float4*)(bp + 4);
            Bs[skg * 8 + 0][sm] = f2tf(v0.x); Bs[skg * 8 + 1][sm] = f2tf(v0.y);
            Bs[skg * 8 + 2][sm] = f2tf(v0.z); Bs[skg * 8 + 3][sm] = f2tf(v0.w);
            Bs[skg * 8 + 4][sm] = f2tf(v1.x); Bs[skg * 8 + 5][sm] = f2tf(v1.y);
            Bs[skg * 8 + 6][sm] = f2tf(v1.z); Bs[skg * 8 + 7][sm] = f2tf(v1.w);
        } else {
            const int bk = tid >> 3;            // 0..31
            const int bn8 = (tid & 7) * 8;
            const float* bp = B + (size_t)(k0 + bk) * Nn + bn + bn8;
            float4 v0 = *(const float4*)bp;
            float4 v1 = *(const float4*)(bp + 4);
            Bs[bk][bn8 + 0] = f2tf(v0.x); Bs[bk][bn8 + 1] = f2tf(v0.y);
            Bs[bk][bn8 + 2] = f2tf(v0.z); Bs[bk][bn8 + 3] = f2tf(v0.w);
            Bs[bk][bn8 + 4] = f2tf(v1.x); Bs[bk][bn8 + 5] = f2tf(v1.y);
            Bs[bk][bn8 + 6] = f2tf(v1.z); Bs[bk][bn8 + 7] = f2tf(v1.w);
        }
        __syncthreads();

        #pragma unroll
        for (int ks = 0; ks < 4; ks++) {
            const int kb = ks * 8;
            uint32_t af[2][4], bf[2][2];
            #pragma unroll
            for (int mt = 0; mt < 2; mt++) {
                const int r = warp_m * 32 + mt * 16;
                af[mt][0] = As[kb + c4][r + g];
                af[mt][1] = As[kb + c4][r + g + 8];
                af[mt][2] = As[kb + c4 + 4][r + g];
                af[mt][3] = As[kb + c4 + 4][r + g + 8];
            }
            #pragma unroll
            for (int nt = 0; nt < 2; nt++) {
                const int cc = warp_n * 16 + nt * 8;
                bf[nt][0] = Bs[kb + c4][cc + g];
                bf[nt][1] = Bs[kb + c4 + 4][cc + g];
            }
            #pragma unroll
            for (int mt = 0; mt < 2; mt++)
                #pragma unroll
                for (int nt = 0; nt < 2; nt++)
                    mma_tf32(acc[mt][nt], af[mt], bf[nt]);
        }
        __syncthreads();
    }

    // ---- epilogue ----
    #pragma unroll
    for (int mt = 0; mt < 2; mt++) {
        #pragma unroll
        for (int nt = 0; nt < 2; nt++) {
            const int col = bn + warp_n * 16 + nt * 8 + c4 * 2;
            #pragma unroll
            for (int rr = 0; rr < 2; rr++) {
                const int row = bm + warp_m * 32 + mt * 16 + g + rr * 8;
                float v0 = acc[mt][nt][rr * 2 + 0];
                float v1 = acc[mt][nt][rr * 2 + 1];
                if (rowscale) { float s = rowscale[row]; v0 *= s; v1 *= s; }
                if (bias)  { v0 += bias[col];  v1 += bias[col + 1]; }
                if (bias2) { v0 += bias2[col]; v1 += bias2[col + 1]; }
                *(float2*)(C + (size_t)row * Nn + col) = make_float2(v0, v1);
            }
        }
    }
}

// ---------------- LSTM gate update ----------------
__global__ void lstm_gate(int use_hh, int first) {
    int idx = blockIdx.x * blockDim.x + threadIdx.x;   // < NNODE*HD
    int n = idx >> 8, f = idx & 255;
    size_t base = (size_t)n * G4;
    float gi = g_gx[base + f];
    float gf = g_gx[base + 256 + f];
    float gg = g_gx[base + 512 + f];
    float go = g_gx[base + 768 + f];
    if (use_hh) {
        gi += g_hhbuf[base + f];
        gf += g_hhbuf[base + 256 + f];
        gg += g_hhbuf[base + 512 + f];
        go += g_hhbuf[base + 768 + f];
    }
    float cp = first ? 0.f : g_c[idx];
    float cn = sigf(gf) * cp + sigf(gi) * tanhf(gg);
    g_c[idx] = cn;
    g_h[idx] = sigf(go) * tanhf(cn);
}

// ---------------- fc epilogue ----------------
__global__ void fc_post(const float* __restrict__ x, float* __restrict__ out_zbar, int k) {
    int idx = blockIdx.x * blockDim.x + threadIdx.x;
    int f = idx & 255;
    float d = tanhf(g_pre[idx]);
    float z = x[idx] + d;
    if (f >= SIG_LO && f < SIG_HI) z = sigf(z);
    out_zbar[(size_t)idx * KEXP + k] = z;
    g_dsum[idx] = (k == 0) ? d : (g_dsum[idx] + d);
}

__global__ void final_pred(const float* __restrict__ x, float* __restrict__ out_pred) {
    int idx = blockIdx.x * blockDim.x + threadIdx.x;
    int f = idx & 255;
    float z = x[idx] + g_dsum[idx] * (1.0f / 3.0f);
    if (f >= SIG_LO && f < SIG_HI) z = sigf(z);
    out_pred[idx] = z;
}

// ---------------- launcher ----------------
extern "C" void kernel_launch(void* const* d_in, const int* in_sizes, int n_in,
                              void* d_out, int out_size) {
    const float* x     = (const float*)d_in[0];
    const float* gnn_w = (const float*)d_in[1];
    const float* gnn_b = (const float*)d_in[2];
    const float* w_ih  = (const float*)d_in[3];
    const float* w_hh  = (const float*)d_in[4];
    const float* b_ih  = (const float*)d_in[5];
    const float* b_hh  = (const float*)d_in[6];
    const float* fc_w  = (const float*)d_in[7];
    const float* fc_b  = (const float*)d_in[8];
    const int*   adj   = (const int*)d_in[9];

    float* out = (float*)d_out;
    float* out_pred = out;                                   // [N, F]
    float* out_zbar = out + (size_t)NNODE * FD;              // [N, F, K]
    float* out_adj  = out + (size_t)NNODE * FD * 4;          // [N, N, K] as float

    float *p_Af, *p_dinv, *p_y, *p_xt, *p_h, *p_gx, *p_hh, *p_pre;
    cudaGetSymbolAddress((void**)&p_Af,   g_Af);
    cudaGetSymbolAddress((void**)&p_dinv, g_dinv);
    cudaGetSymbolAddress((void**)&p_y,    g_y);
    cudaGetSymbolAddress((void**)&p_xt,   g_xt);
    cudaGetSymbolAddress((void**)&p_h,    g_h);
    cudaGetSymbolAddress((void**)&p_gx,   g_gx);
    cudaGetSymbolAddress((void**)&p_hh,   g_hhbuf);
    cudaGetSymbolAddress((void**)&p_pre,  g_pre);

    prep_kernel<<<NNODE, 256>>>(adj, out_adj);

    const int EW_BLOCKS = (NNODE * FD) / 256;
    const dim3 blk(256);
    const dim3 gr_h(HD / 64, NNODE / 64);       // Nn = 256
    const dim3 gr_g(G4 / 64, NNODE / 64);       // Nn = 1024

    for (int k = 0; k < KEXP; k++) {
        const float* dinv_k = p_dinv + (size_t)k * NNODE;

        // y = dinv * (x @ gnn_w[k])        [NN GEMM 4096x256x256]
        mma_gemm<0><<<gr_h, blk>>>(x, gnn_w + (size_t)k * FD * HD,
                                   dinv_k, nullptr, nullptr, p_y, HD, FD);
        // xt = dinv * (A_k @ y) + gnn_b    [NN GEMM 4096x256x4096]
        mma_gemm<0><<<gr_h, blk>>>(p_Af + (size_t)k * NNODE * NNODE, p_y,
                                   dinv_k, gnn_b + (size_t)k * HD, nullptr, p_xt, HD, NNODE);
        // gx = xt @ w_ih^T + b_ih + b_hh   [NT GEMM 4096x1024x256] (time-invariant)
        mma_gemm<1><<<gr_g, blk>>>(p_xt, w_ih + (size_t)k * G4 * HD,
                                   nullptr, b_ih + (size_t)k * G4, b_hh + (size_t)k * G4,
                                   p_gx, G4, HD);

        lstm_gate<<<EW_BLOCKS, 256>>>(0, 1);   // t=0: h=c=0
        for (int t = 1; t < TSTEP; t++) {
            mma_gemm<1><<<gr_g, blk>>>(p_h, w_hh + (size_t)k * G4 * HD,
                                       nullptr, nullptr, nullptr, p_hh, G4, HD);
            lstm_gate<<<EW_BLOCKS, 256>>>(1, 0);
        }

        // pre = h @ fc_w^T + fc_b          [NT GEMM 4096x256x256]
        mma_gemm<1><<<gr_h, blk>>>(p_h, fc_w + (size_t)k * FD * HD,
                                   nullptr, fc_b + (size_t)k * FD, nullptr, p_pre, FD, HD);
        fc_post<<<EW_BLOCKS, 256>>>(x, out_zbar, k);
    }

    final_pred<<<EW_BLOCKS, 256>>>(x, out_pred);
}

// round 3
// speedup vs baseline: 2.7168x; 2.1508x over previous
#include <cuda_runtime.h>
#include <cuda_bf16.h>
#include <cstdint>

#define NNODE 4096
#define FD 256
#define HD 256
#define KEXP 3
#define TSTEP 5
#define G4 1024
#define SIG_LO 10
#define SIG_HI 253   // F_DIM - END

// ---------------- scratch (device globals: no allocation allowed) ----------------
__device__ float g_Af[KEXP][(size_t)NNODE * NNODE];   // a_bin + I, values {0,1,2}
__device__ float g_dinv[KEXP][NNODE];
__device__ float g_y[(size_t)NNODE * HD];
__device__ float g_xt[(size_t)NNODE * HD];
__device__ float g_gx[(size_t)NNODE * G4];
__device__ float g_hhbuf[(size_t)NNODE * G4];
__device__ float g_h[(size_t)NNODE * HD];
__device__ float g_c[(size_t)NNODE * HD];
__device__ float g_pre[(size_t)NNODE * FD];
__device__ float g_dsum[(size_t)NNODE * FD];

__device__ __forceinline__ float sigf(float v) { return 1.0f / (1.0f + expf(-v)); }

__device__ __forceinline__ void mma_tf32(float c[4], const uint32_t a[4], const uint32_t b[2]) {
    asm volatile(
        "mma.sync.aligned.m16n8k8.row.col.f32.tf32.tf32.f32 "
        "{%0,%1,%2,%3}, {%4,%5,%6,%7}, {%8,%9}, {%0,%1,%2,%3};"
        : "+f"(c[0]), "+f"(c[1]), "+f"(c[2]), "+f"(c[3])
        : "r"(a[0]), "r"(a[1]), "r"(a[2]), "r"(a[3]), "r"(b[0]), "r"(b[1]));
}

__device__ __forceinline__ void cp16(float* sdst, const float* gsrc) {
    uint32_t s = (uint32_t)__cvta_generic_to_shared(sdst);
    asm volatile("cp.async.cg.shared.global [%0], [%1], 16;\n" :: "r"(s), "l"(gsrc));
}
__device__ __forceinline__ void cp_commit() { asm volatile("cp.async.commit_group;\n"); }
template <int N>
__device__ __forceinline__ void cp_wait() { asm volatile("cp.async.wait_group %0;\n" :: "n"(N)); }

__device__ __forceinline__ uint32_t fbits(float f) { return __float_as_uint(f); }

// ---------------- prep: one coalesced pass over adj ----------------
__global__ void prep_kernel(const int* __restrict__ adj, float* __restrict__ out_adj) {
    const int i = blockIdx.x;
    const int tid = threadIdx.x;
    const int* row = adj + (size_t)i * NNODE * KEXP;
    float* orow = out_adj + (size_t)i * NNODE * KEXP;
    float* A0 = &g_Af[0][(size_t)i * NNODE];
    float* A1 = &g_Af[1][(size_t)i * NNODE];
    float* A2 = &g_Af[2][(size_t)i * NNODE];
    float s0 = 0.f, s1 = 0.f, s2 = 0.f;
    for (int j = tid; j < NNODE; j += 256) {
        int b = j * 3;
        int a0 = row[b + 0], a1 = row[b + 1], a2 = row[b + 2];
        float v0 = a0 ? 1.f : 0.f, v1 = a1 ? 1.f : 0.f, v2 = a2 ? 1.f : 0.f;
        if (j == i) { v0 += 1.f; v1 += 1.f; v2 += 1.f; }
        A0[j] = v0; A1[j] = v1; A2[j] = v2;
        orow[b + 0] = (float)a0; orow[b + 1] = (float)a1; orow[b + 2] = (float)a2;
        s0 += v0; s1 += v1; s2 += v2;
    }
    __shared__ float sh[3][256];
    sh[0][tid] = s0; sh[1][tid] = s1; sh[2][tid] = s2;
    __syncthreads();
    for (int off = 128; off > 0; off >>= 1) {
        if (tid < off) {
            sh[0][tid] += sh[0][tid + off];
            sh[1][tid] += sh[1][tid + off];
            sh[2][tid] += sh[2][tid + off];
        }
        __syncthreads();
    }
    if (tid < 3) g_dinv[tid][i] = rsqrtf(sh[tid][0]);
}

// ---------------- TF32 tensor-core GEMM, cp.async double-buffered ----------------
// C[M,Nn] = A[M,Kd] @ op(B)  (+ rowscale, + bias, + bias2)
// TRANSB=0: B is [Kd,Nn] row-major.  TRANSB=1: B is [Nn,Kd] row-major.
// Block tile BM x 128 x 32, 256 threads = 8 warps (2 x 4), warp tile (BM/2) x 32.
// Raw fp32 bits fed to tf32 mma (HW truncates mantissa).
#define APAD 44    // 32 + 12  -> conflict-free [m][k] / [n][k] frag loads
#define BPAD 136   // 128 + 8  -> conflict-free [k][n] frag loads

template <int TRANSB, int BM>
__global__ void __launch_bounds__(256, 1) mma_gemm(
    const float* __restrict__ A, const float* __restrict__ B,
    const float* __restrict__ rowscale, const float* __restrict__ bias,
    const float* __restrict__ bias2, float* __restrict__ C, int Nn, int Kd) {

    constexpr int MT = BM / 32;               // m16 tiles per warp (2 or 4)
    constexpr int AS_STAGE = BM * APAD;
    constexpr int BS_STAGE = TRANSB ? (128 * APAD) : (32 * BPAD);
    constexpr int A_CHUNKS = BM / 32;         // 16B chunks per thread per stage

    extern __shared__ float smem[];
    float* As = smem;                          // [2][BM][APAD]
    float* Bs = smem + 2 * AS_STAGE;           // [2][...]

    const int tid = threadIdx.x;
    const int wid = tid >> 5, lane = tid & 31;
    const int warp_m = wid >> 2;               // 0..1
    const int warp_n = wid & 3;                // 0..3
    const int g = lane >> 2, c4 = lane & 3;
    const int bm = blockIdx.y * BM, bn = blockIdx.x * 128;

    const int nIter = Kd >> 5;

    auto issue = [&](int p, int it) {
        const int k0 = it << 5;
        // A tile: BM rows x 32 floats, 8 chunks/row
        #pragma unroll
        for (int q = 0; q < A_CHUNKS; q++) {
            int id = tid + 256 * q;
            int m = id >> 3, c = id & 7;
            cp16(As + p * AS_STAGE + m * APAD + c * 4,
                 A + (size_t)(bm + m) * Kd + k0 + c * 4);
        }
        if (TRANSB) {
            // B tile: 128 n-rows x 32 k, [n][k]
            #pragma unroll
            for (int q = 0; q < 4; q++) {
                int id = tid + 256 * q;
                int n = id >> 3, c = id & 7;
                cp16(Bs + p * BS_STAGE + n * APAD + c * 4,
                     B + (size_t)(bn + n) * Kd + k0 + c * 4);
            }
        } else {
            // B tile: 32 k-rows x 128 n, [k][n]
            #pragma unroll
            for (int q = 0; q < 4; q++) {
                int id = tid + 256 * q;
                int kr = id >> 5, c = id & 31;
                cp16(Bs + p * BS_STAGE + kr * BPAD + c * 4,
                     B + (size_t)(k0 + kr) * Nn + bn + c * 4);
            }
        }
    };

    float acc[MT][4][4] = {};

    issue(0, 0); cp_commit();
    issue(1, 1); cp_commit();

    for (int i = 0; i < nIter; i++) {
        const int p = i & 1;
        cp_wait<1>();
        __syncthreads();

        const float* Ab = As + p * AS_STAGE;
        const float* Bb = Bs + p * BS_STAGE;
        #pragma unroll
        for (int ks = 0; ks < 4; ks++) {
            const int kb = ks * 8;
            uint32_t af[MT][4], bf[4][2];
            #pragma unroll
            for (int mt = 0; mt < MT; mt++) {
                const float* pa = Ab + (warp_m * (BM / 2) + mt * 16 + g) * APAD + kb + c4;
                af[mt][0] = fbits(pa[0]);
                af[mt][1] = fbits(pa[8 * APAD]);
                af[mt][2] = fbits(pa[4]);
                af[mt][3] = fbits(pa[8 * APAD + 4]);
            }
            #pragma unroll
            for (int nt = 0; nt < 4; nt++) {
                if (TRANSB) {
                    const float* pb = Bb + (warp_n * 32 + nt * 8 + g) * APAD + kb + c4;
                    bf[nt][0] = fbits(pb[0]);
                    bf[nt][1] = fbits(pb[4]);
                } else {
                    const float* pb = Bb + (kb + c4) * BPAD + warp_n * 32 + nt * 8 + g;
                    bf[nt][0] = fbits(pb[0]);
                    bf[nt][1] = fbits(pb[4 * BPAD]);
                }
            }
            #pragma unroll
            for (int mt = 0; mt < MT; mt++)
                #pragma unroll
                for (int nt = 0; nt < 4; nt++)
                    mma_tf32(acc[mt][nt], af[mt], bf[nt]);
        }
        __syncthreads();
        if (i + 2 < nIter) issue(p, i + 2);
        cp_commit();
    }

    // ---- epilogue ----
    #pragma unroll
    for (int mt = 0; mt < MT; mt++) {
        #pragma unroll
        for (int nt = 0; nt < 4; nt++) {
            const int col = bn + warp_n * 32 + nt * 8 + c4 * 2;
            #pragma unroll
            for (int rr = 0; rr < 2; rr++) {
                const int row = bm + warp_m * (BM / 2) + mt * 16 + g + rr * 8;
                float v0 = acc[mt][nt][rr * 2 + 0];
                float v1 = acc[mt][nt][rr * 2 + 1];
                if (rowscale) { float s = rowscale[row]; v0 *= s; v1 *= s; }
                if (bias)  { v0 += bias[col];  v1 += bias[col + 1]; }
                if (bias2) { v0 += bias2[col]; v1 += bias2[col + 1]; }
                *(float2*)(C + (size_t)row * Nn + col) = make_float2(v0, v1);
            }
        }
    }
}

// ---------------- LSTM gate update ----------------
__global__ void lstm_gate(int use_hh, int first) {
    int idx = blockIdx.x * blockDim.x + threadIdx.x;
    int n = idx >> 8, f = idx & 255;
    size_t base = (size_t)n * G4;
    float gi = g_gx[base + f];
    float gf = g_gx[base + 256 + f];
    float gg = g_gx[base + 512 + f];
    float go = g_gx[base + 768 + f];
    if (use_hh) {
        gi += g_hhbuf[base + f];
        gf += g_hhbuf[base + 256 + f];
        gg += g_hhbuf[base + 512 + f];
        go += g_hhbuf[base + 768 + f];
    }
    float cp = first ? 0.f : g_c[idx];
    float cn = sigf(gf) * cp + sigf(gi) * tanhf(gg);
    g_c[idx] = cn;
    g_h[idx] = sigf(go) * tanhf(cn);
}

// ---------------- fc epilogue ----------------
__global__ void fc_post(const float* __restrict__ x, float* __restrict__ out_zbar, int k) {
    int idx = blockIdx.x * blockDim.x + threadIdx.x;
    int f = idx & 255;
    float d = tanhf(g_pre[idx]);
    float z = x[idx] + d;
    if (f >= SIG_LO && f < SIG_HI) z = sigf(z);
    out_zbar[(size_t)idx * KEXP + k] = z;
    g_dsum[idx] = (k == 0) ? d : (g_dsum[idx] + d);
}

__global__ void final_pred(const float* __restrict__ x, float* __restrict__ out_pred) {
    int idx = blockIdx.x * blockDim.x + threadIdx.x;
    int f = idx & 255;
    float z = x[idx] + g_dsum[idx] * (1.0f / 3.0f);
    if (f >= SIG_LO && f < SIG_HI) z = sigf(z);
    out_pred[idx] = z;
}

// ---------------- launcher ----------------
extern "C" void kernel_launch(void* const* d_in, const int* in_sizes, int n_in,
                              void* d_out, int out_size) {
    const float* x     = (const float*)d_in[0];
    const float* gnn_w = (const float*)d_in[1];
    const float* gnn_b = (const float*)d_in[2];
    const float* w_ih  = (const float*)d_in[3];
    const float* w_hh  = (const float*)d_in[4];
    const float* b_ih  = (const float*)d_in[5];
    const float* b_hh  = (const float*)d_in[6];
    const float* fc_w  = (const float*)d_in[7];
    const float* fc_b  = (const float*)d_in[8];
    const int*   adj   = (const int*)d_in[9];

    float* out = (float*)d_out;
    float* out_pred = out;
    float* out_zbar = out + (size_t)NNODE * FD;
    float* out_adj  = out + (size_t)NNODE * FD * 4;

    float *p_Af, *p_dinv, *p_y, *p_xt, *p_h, *p_gx, *p_hh, *p_pre;
    cudaGetSymbolAddress((void**)&p_Af,   g_Af);
    cudaGetSymbolAddress((void**)&p_dinv, g_dinv);
    cudaGetSymbolAddress((void**)&p_y,    g_y);
    cudaGetSymbolAddress((void**)&p_xt,   g_xt);
    cudaGetSymbolAddress((void**)&p_h,    g_h);
    cudaGetSymbolAddress((void**)&p_gx,   g_gx);
    cudaGetSymbolAddress((void**)&p_hh,   g_hhbuf);
    cudaGetSymbolAddress((void**)&p_pre,  g_pre);

    // dynamic smem sizes (bytes)
    const int smem_nn64  = (2 * 64 * APAD + 2 * 32 * BPAD) * 4;    // 57344
    const int smem_nt64  = (2 * 64 * APAD + 2 * 128 * APAD) * 4;   // 67584
    const int smem_nt128 = (2 * 128 * APAD + 2 * 128 * APAD) * 4;  // 90112
    cudaFuncSetAttribute(mma_gemm<0, 64>,  cudaFuncAttributeMaxDynamicSharedMemorySize, smem_nn64);
    cudaFuncSetAttribute(mma_gemm<1, 64>,  cudaFuncAttributeMaxDynamicSharedMemorySize, smem_nt64);
    cudaFuncSetAttribute(mma_gemm<1, 128>, cudaFuncAttributeMaxDynamicSharedMemorySize, smem_nt128);

    prep_kernel<<<NNODE, 256>>>(adj, out_adj);

    const int EW_BLOCKS = (NNODE * FD) / 256;
    const dim3 blk(256);
    const dim3 gr_h64(HD / 128, NNODE / 64);     // (2, 64) for Nn=256, BM=64
    const dim3 gr_g128(G4 / 128, NNODE / 128);   // (8, 32) for Nn=1024, BM=128

    for (int k = 0; k < KEXP; k++) {
        const float* dinv_k = p_dinv + (size_t)k * NNODE;

        // y = dinv * (x @ gnn_w[k])        [NN 4096x256x256]
        mma_gemm<0, 64><<<gr_h64, blk, smem_nn64>>>(
            x, gnn_w + (size_t)k * FD * HD, dinv_k, nullptr, nullptr, p_y, HD, FD);
        // xt = dinv * (A_k @ y) + gnn_b    [NN 4096x256x4096]
        mma_gemm<0, 64><<<gr_h64, blk, smem_nn64>>>(
            p_Af + (size_t)k * NNODE * NNODE, p_y, dinv_k,
            gnn_b + (size_t)k * HD, nullptr, p_xt, HD, NNODE);
        // gx = xt @ w_ih^T + b_ih + b_hh   [NT 4096x1024x256]
        mma_gemm<1, 128><<<gr_g128, blk, smem_nt128>>>(
            p_xt, w_ih + (size_t)k * G4 * HD, nullptr,
            b_ih + (size_t)k * G4, b_hh + (size_t)k * G4, p_gx, G4, HD);

        lstm_gate<<<EW_BLOCKS, 256>>>(0, 1);
        for (int t = 1; t < TSTEP; t++) {
            mma_gemm<1, 128><<<gr_g128, blk, smem_nt128>>>(
                p_h, w_hh + (size_t)k * G4 * HD, nullptr, nullptr, nullptr, p_hh, G4, HD);
            lstm_gate<<<EW_BLOCKS, 256>>>(1, 0);
        }

        // pre = h @ fc_w^T + fc_b          [NT 4096x256x256]
        mma_gemm<1, 64><<<gr_h64, blk, smem_nt64>>>(
            p_h, fc_w + (size_t)k * FD * HD, nullptr,
            fc_b + (size_t)k * FD, nullptr, p_pre, FD, HD);
        fc_post<<<EW_BLOCKS, 256>>>(x, out_zbar, k);
    }

    final_pred<<<EW_BLOCKS, 256>>>(x, out_pred);
}